// round 12
// baseline (speedup 1.0000x reference)
#include <cuda_runtime.h>
#include <cstdint>
#include <math.h>

#define DEPTH 12
#define DIM   768
#define NH    12
#define HD    64
#define NTOK  577
#define BATCH 8
#define HID   3072
#define NCLS  1000
#define NPATCH 576
#define ROWS  (BATCH * NTOK)      // 4616
#define QKVW  (3 * DIM)           // 2304
#define SCR   640                 // padded g_scores row stride

// ---------------- scratch (device globals; allocation-free) ----------------
__device__ float g_h[ROWS * DIM];
__device__ float g_qkv[ROWS * QKVW];
__device__ float g_scores[BATCH * NH * NTOK * SCR];   // padded rows
__device__ float g_o[ROWS * DIM];
__device__ float g_mid[ROWS * HID];
__device__ float g_patches[BATCH * NPATCH * DIM];
__device__ float g_tmp[BATCH * NPATCH * DIM];
__device__ float g_lnm[ROWS];
__device__ float g_lnr[ROWS];
__device__ float g_cls[BATCH * DIM];
__device__ float g_qkvT[DEPTH * QKVW * DIM];
__device__ float g_projT[DEPTH * DIM * DIM];
__device__ float g_w1T[DEPTH * HID * DIM];
__device__ float g_w2T[DEPTH * DIM * HID];

// ====================== mma helpers ========================================
__device__ __forceinline__ uint32_t cvt_tf32(float f) {
    uint32_t u;
    asm("cvt.rna.tf32.f32 %0, %1;" : "=r"(u) : "f"(f));
    return u;
}

__device__ __forceinline__ void mma_tf32(float* c, const uint32_t* a, const uint32_t* b) {
    asm volatile(
        "mma.sync.aligned.m16n8k8.row.col.f32.tf32.tf32.f32 "
        "{%0,%1,%2,%3}, {%4,%5,%6,%7}, {%8,%9}, {%0,%1,%2,%3};"
        : "+f"(c[0]), "+f"(c[1]), "+f"(c[2]), "+f"(c[3])
        : "r"(a[0]), "r"(a[1]), "r"(a[2]), "r"(a[3]), "r"(b[0]), "r"(b[1]));
}

__device__ __forceinline__ void split4(float4 v, float4& hi, float4& lo) {
    hi.x = __uint_as_float(cvt_tf32(v.x)); lo.x = __uint_as_float(cvt_tf32(v.x - hi.x));
    hi.y = __uint_as_float(cvt_tf32(v.y)); lo.y = __uint_as_float(cvt_tf32(v.y - hi.y));
    hi.z = __uint_as_float(cvt_tf32(v.z)); lo.z = __uint_as_float(cvt_tf32(v.z - hi.z));
    hi.w = __uint_as_float(cvt_tf32(v.w)); lo.w = __uint_as_float(cvt_tf32(v.w - hi.w));
}

// ====================== tf32 mma.sync dense GEMM ===========================
#define SMS 36
#define TILE_F (128 * SMS)
#define GEMM_SMEM (4 * TILE_F * 4)  // 73728 B

template <bool LNA>
__device__ __forceinline__ void load_chunk_g(const float* __restrict__ A,
                                             const float* __restrict__ BT,
                                             const float* __restrict__ lnG,
                                             const float* __restrict__ lnB,
                                             int M, int K, int row0, int col0,
                                             int k0, float* dA, float* dB, int tid) {
    float4 va[4], vb[4];
#pragma unroll
    for (int i = 0; i < 4; i++) {
        int f4 = tid + i * 256;
        int r = f4 >> 3, cc = (f4 & 7) * 4;
        int gr = row0 + r;
        va[i] = make_float4(0.f, 0.f, 0.f, 0.f);
        if (gr < M) {
            va[i] = *(const float4*)(A + (size_t)gr * K + k0 + cc);
            if (LNA) {
                float mm = g_lnm[gr], rr = g_lnr[gr];
                float4 gam = *(const float4*)(lnG + k0 + cc);
                float4 bet = *(const float4*)(lnB + k0 + cc);
                va[i].x = (va[i].x - mm) * rr * gam.x + bet.x;
                va[i].y = (va[i].y - mm) * rr * gam.y + bet.y;
                va[i].z = (va[i].z - mm) * rr * gam.z + bet.z;
                va[i].w = (va[i].w - mm) * rr * gam.w + bet.w;
            }
        }
        vb[i] = *(const float4*)(BT + (size_t)(col0 + r) * K + k0 + cc);
    }
#pragma unroll
    for (int i = 0; i < 4; i++) {
        int f4 = tid + i * 256;
        int r = f4 >> 3, cc = (f4 & 7) * 4;
        float4 ca, cb;
        ca.x = __uint_as_float(cvt_tf32(va[i].x));
        ca.y = __uint_as_float(cvt_tf32(va[i].y));
        ca.z = __uint_as_float(cvt_tf32(va[i].z));
        ca.w = __uint_as_float(cvt_tf32(va[i].w));
        cb.x = __uint_as_float(cvt_tf32(vb[i].x));
        cb.y = __uint_as_float(cvt_tf32(vb[i].y));
        cb.z = __uint_as_float(cvt_tf32(vb[i].z));
        cb.w = __uint_as_float(cvt_tf32(vb[i].w));
        *(float4*)&dA[r * SMS + cc] = ca;
        *(float4*)&dB[r * SMS + cc] = cb;
    }
}

// EPI: 0 = bias, 1 = bias+GELU(exact), 2 = bias+residual
template <int EPI, bool LNA>
__global__ void __launch_bounds__(256, 2)
gemm_mma(const float* __restrict__ A, const float* __restrict__ BT,
         const float* __restrict__ bias, const float* __restrict__ res,
         const float* __restrict__ lnG, const float* __restrict__ lnB,
         float* __restrict__ C, int M, int N, int K) {
    extern __shared__ float sm[];
    float* As = sm;
    float* Bs = sm + 2 * TILE_F;
    const int tid = threadIdx.x;
    const int w = tid >> 5, lane = tid & 31;
    const int g = lane >> 2, t = lane & 3;
    const int warp_m = (w & 1) * 64, warp_n = (w >> 1) * 32;
    const int row0 = blockIdx.y * 128, col0 = blockIdx.x * 128;

    float acc[4][4][4] = {};
    const int NC = K / 32;

    load_chunk_g<LNA>(A, BT, lnG, lnB, M, K, row0, col0, 0, As, Bs, tid);
    __syncthreads();

    for (int ch = 0; ch < NC; ch++) {
        int buf = ch & 1;
        if (ch + 1 < NC)
            load_chunk_g<LNA>(A, BT, lnG, lnB, M, K, row0, col0, (ch + 1) * 32,
                              As + (buf ^ 1) * TILE_F, Bs + (buf ^ 1) * TILE_F, tid);
        const uint32_t* sA = (const uint32_t*)(As + buf * TILE_F);
        const uint32_t* sB = (const uint32_t*)(Bs + buf * TILE_F);
#pragma unroll
        for (int ks = 0; ks < 4; ks++) {
            int k0 = ks * 8;
            uint32_t a[4][4], b[4][2];
#pragma unroll
            for (int mt = 0; mt < 4; mt++) {
                int rb = (warp_m + mt * 16 + g) * SMS + k0 + t;
                a[mt][0] = sA[rb];
                a[mt][1] = sA[rb + 8 * SMS];
                a[mt][2] = sA[rb + 4];
                a[mt][3] = sA[rb + 8 * SMS + 4];
            }
#pragma unroll
            for (int nt = 0; nt < 4; nt++) {
                int rb = (warp_n + nt * 8 + g) * SMS + k0 + t;
                b[nt][0] = sB[rb];
                b[nt][1] = sB[rb + 4];
            }
#pragma unroll
            for (int mt = 0; mt < 4; mt++)
#pragma unroll
                for (int nt = 0; nt < 4; nt++)
                    mma_tf32(acc[mt][nt], a[mt], b[nt]);
        }
        __syncthreads();
    }

#pragma unroll
    for (int mt = 0; mt < 4; mt++) {
#pragma unroll
        for (int half = 0; half < 2; half++) {
            int r = row0 + warp_m + mt * 16 + g + half * 8;
            if (r >= M) continue;
            float* crow = C + (size_t)r * N;
            const float* rrow = (EPI == 2) ? res + (size_t)r * N : nullptr;
#pragma unroll
            for (int nt = 0; nt < 4; nt++) {
                int col = col0 + warp_n + nt * 8 + 2 * t;
                float v0 = acc[mt][nt][half * 2 + 0] + bias[col];
                float v1 = acc[mt][nt][half * 2 + 1] + bias[col + 1];
                if (EPI == 1) {
                    v0 = 0.5f * v0 * (1.f + erff(v0 * 0.70710678118654752f));
                    v1 = 0.5f * v1 * (1.f + erff(v1 * 0.70710678118654752f));
                }
                if (EPI == 2) {
                    v0 += rrow[col];
                    v1 += rrow[col + 1];
                }
                *(float2*)&crow[col] = make_float2(v0, v1);
            }
        }
    }
}

// ---------------- weight transpose -----------------------------------------
__global__ void transpose_kernel(const float* __restrict__ src, float* __restrict__ dst,
                                 int K, int N) {
    __shared__ float t[32][33];
    const float* s = src + (size_t)blockIdx.z * K * N;
    float* d = dst + (size_t)blockIdx.z * K * N;
    int k0 = blockIdx.y * 32, n0 = blockIdx.x * 32;
    int x = threadIdx.x, y = threadIdx.y;
#pragma unroll
    for (int i = 0; i < 32; i += 8)
        t[y + i][x] = s[(size_t)(k0 + y + i) * N + n0 + x];
    __syncthreads();
#pragma unroll
    for (int i = 0; i < 32; i += 8)
        d[(size_t)(n0 + y + i) * K + k0 + x] = t[x][y + i];
}

// ---------------- LN row stats ---------------------------------------------
__global__ void ln_stats_kernel(const float* __restrict__ x, float eps) {
    int row = blockIdx.x;
    const float* xr = x + (size_t)row * DIM;
    int tid = threadIdx.x;
    float v0 = xr[tid], v1 = xr[tid + 256], v2 = xr[tid + 512];
    float s = v0 + v1 + v2;
    float sq = v0 * v0 + v1 * v1 + v2 * v2;
#pragma unroll
    for (int o = 16; o; o >>= 1) {
        s  += __shfl_xor_sync(0xffffffffu, s, o);
        sq += __shfl_xor_sync(0xffffffffu, sq, o);
    }
    __shared__ float ss[8], ssq[8];
    int w = tid >> 5, l = tid & 31;
    if (l == 0) { ss[w] = s; ssq[w] = sq; }
    __syncthreads();
    if (tid == 0) {
        float ts = 0.f, tq = 0.f;
        for (int i = 0; i < 8; i++) { ts += ss[i]; tq += ssq[i]; }
        float m = ts * (1.f / DIM);
        float var = tq * (1.f / DIM) - m * m;
        g_lnm[row] = m;
        g_lnr[row] = rsqrtf(var + eps);
    }
}

// ---------------- final LN (cls rows only) ---------------------------------
__global__ void ln_cls_kernel(const float* __restrict__ g, const float* __restrict__ b,
                              float eps) {
    int bb = blockIdx.x;
    const float* xr = g_h + (size_t)bb * NTOK * DIM;
    int tid = threadIdx.x;
    float v0 = xr[tid], v1 = xr[tid + 256], v2 = xr[tid + 512];
    float s = v0 + v1 + v2;
    float sq = v0 * v0 + v1 * v1 + v2 * v2;
#pragma unroll
    for (int o = 16; o; o >>= 1) {
        s  += __shfl_xor_sync(0xffffffffu, s, o);
        sq += __shfl_xor_sync(0xffffffffu, sq, o);
    }
    __shared__ float ss[8], ssq[8], red[2];
    int w = tid >> 5, l = tid & 31;
    if (l == 0) { ss[w] = s; ssq[w] = sq; }
    __syncthreads();
    if (tid == 0) {
        float ts = 0.f, tq = 0.f;
        for (int i = 0; i < 8; i++) { ts += ss[i]; tq += ssq[i]; }
        float m = ts * (1.f / DIM);
        float var = tq * (1.f / DIM) - m * m;
        red[0] = m;
        red[1] = rsqrtf(var + eps);
    }
    __syncthreads();
    float m = red[0], r = red[1];
    float* yr = g_cls + bb * DIM;
    yr[tid]       = (v0 - m) * r * g[tid]       + b[tid];
    yr[tid + 256] = (v1 - m) * r * g[tid + 256] + b[tid + 256];
    yr[tid + 512] = (v2 - m) * r * g[tid + 512] + b[tid + 512];
}

// ---------------- attention scores via 3xtf32 mma --------------------------
// grid (10 kj, 10 qi, B*NH), 256 thr. S = (Q K^T)/8, fp32-accurate.
#define ATT_T (64 * 68)
#define ATT_SMEM (4 * ATT_T * 4)   // 69632 B

__global__ void __launch_bounds__(256, 2) attn_scores_mma() {
    extern __shared__ float s_[];
    float* Qhi = s_;
    float* Qlo = s_ + ATT_T;
    float* Khi = s_ + 2 * ATT_T;
    float* Klo = s_ + 3 * ATT_T;
    int z = blockIdx.z;
    int b = z / NH, h = z % NH;
    int qi0 = blockIdx.y * 64, kj0 = blockIdx.x * 64;
    int tid = threadIdx.x;
    int fr = tid >> 4, fc4 = (tid & 15) * 4;
    const float* qbase = g_qkv + (size_t)b * NTOK * QKVW + h * HD;
    const float* kbase = qbase + DIM;
#pragma unroll
    for (int rr = 0; rr < 64; rr += 16) {
        int qn = qi0 + fr + rr;
        float4 v = make_float4(0.f, 0.f, 0.f, 0.f);
        if (qn < NTOK) v = *(const float4*)(qbase + (size_t)qn * QKVW + fc4);
        float4 hi, lo;
        split4(v, hi, lo);
        *(float4*)&Qhi[(fr + rr) * 68 + fc4] = hi;
        *(float4*)&Qlo[(fr + rr) * 68 + fc4] = lo;
        int kn = kj0 + fr + rr;
        float4 kv = make_float4(0.f, 0.f, 0.f, 0.f);
        if (kn < NTOK) kv = *(const float4*)(kbase + (size_t)kn * QKVW + fc4);
        split4(kv, hi, lo);
        *(float4*)&Khi[(fr + rr) * 68 + fc4] = hi;
        *(float4*)&Klo[(fr + rr) * 68 + fc4] = lo;
    }
    __syncthreads();

    int w = tid >> 5, lane = tid & 31;
    int g = lane >> 2, t = lane & 3;
    int warp_m = (w & 1) * 32, warp_n = (w >> 1) * 16;
    const uint32_t* qh = (const uint32_t*)Qhi;
    const uint32_t* ql = (const uint32_t*)Qlo;
    const uint32_t* kh = (const uint32_t*)Khi;
    const uint32_t* kl = (const uint32_t*)Klo;
    float acc[2][2][4] = {};
#pragma unroll
    for (int ks = 0; ks < 8; ks++) {
        int k0 = ks * 8;
        uint32_t ah[2][4], al[2][4], bh[2][2], bl[2][2];
#pragma unroll
        for (int mt = 0; mt < 2; mt++) {
            int rb = (warp_m + mt * 16 + g) * 68 + k0 + t;
            ah[mt][0] = qh[rb]; ah[mt][1] = qh[rb + 8 * 68];
            ah[mt][2] = qh[rb + 4]; ah[mt][3] = qh[rb + 8 * 68 + 4];
            al[mt][0] = ql[rb]; al[mt][1] = ql[rb + 8 * 68];
            al[mt][2] = ql[rb + 4]; al[mt][3] = ql[rb + 8 * 68 + 4];
        }
#pragma unroll
        for (int nt = 0; nt < 2; nt++) {
            int rb = (warp_n + nt * 8 + g) * 68 + k0 + t;
            bh[nt][0] = kh[rb]; bh[nt][1] = kh[rb + 4];
            bl[nt][0] = kl[rb]; bl[nt][1] = kl[rb + 4];
        }
#pragma unroll
        for (int mt = 0; mt < 2; mt++)
#pragma unroll
            for (int nt = 0; nt < 2; nt++) {
                mma_tf32(acc[mt][nt], ah[mt], bh[nt]);
                mma_tf32(acc[mt][nt], ah[mt], bl[nt]);
                mma_tf32(acc[mt][nt], al[mt], bh[nt]);
            }
    }
    float* sbuf = g_scores + (size_t)z * NTOK * SCR;
#pragma unroll
    for (int mt = 0; mt < 2; mt++)
#pragma unroll
        for (int half = 0; half < 2; half++) {
            int row = qi0 + warp_m + mt * 16 + g + half * 8;
            if (row >= NTOK) continue;
#pragma unroll
            for (int nt = 0; nt < 2; nt++) {
                int col = kj0 + warp_n + nt * 8 + 2 * t;
                *(float2*)&sbuf[(size_t)row * SCR + col] =
                    make_float2(acc[mt][nt][half * 2] * 0.125f,
                                acc[mt][nt][half * 2 + 1] * 0.125f);
            }
        }
}

// ---------------- softmax over rows of 577 (stride SCR) --------------------
__global__ void softmax_kernel() {
    float* p = g_scores + (size_t)blockIdx.y * NTOK * SCR + (size_t)blockIdx.x * SCR;
    int tid = threadIdx.x;
    float v[3];
    float mx = -1e30f;
#pragma unroll
    for (int i = 0; i < 3; i++) {
        int idx = tid + i * 256;
        v[i] = (idx < NTOK) ? p[idx] : -1e30f;
        mx = fmaxf(mx, v[i]);
    }
#pragma unroll
    for (int o = 16; o; o >>= 1) mx = fmaxf(mx, __shfl_xor_sync(0xffffffffu, mx, o));
    __shared__ float sm_[8], sred[2];
    int w = tid >> 5, l = tid & 31;
    if (l == 0) sm_[w] = mx;
    __syncthreads();
    if (tid == 0) {
        float tt = sm_[0];
        for (int i = 1; i < 8; i++) tt = fmaxf(tt, sm_[i]);
        sred[0] = tt;
    }
    __syncthreads();
    mx = sred[0];
    float sum = 0.f;
#pragma unroll
    for (int i = 0; i < 3; i++) {
        int idx = tid + i * 256;
        if (idx < NTOK) { v[i] = expf(v[i] - mx); sum += v[i]; }
    }
#pragma unroll
    for (int o = 16; o; o >>= 1) sum += __shfl_xor_sync(0xffffffffu, sum, o);
    __syncthreads();
    if (l == 0) sm_[w] = sum;
    __syncthreads();
    if (tid == 0) {
        float tt = 0.f;
        for (int i = 0; i < 8; i++) tt += sm_[i];
        sred[1] = 1.f / tt;
    }
    __syncthreads();
    float inv = sred[1];
#pragma unroll
    for (int i = 0; i < 3; i++) {
        int idx = tid + i * 256;
        if (idx < NTOK) p[idx] = v[i] * inv;
    }
}

// ---------------- attention out via 3xtf32 mma -----------------------------
// grid (10 qi, B*NH), 256 thr. O = P @ V, K-dim = 577 in 10 chunks of 64.
__global__ void __launch_bounds__(256, 2) attn_out_mma() {
    extern __shared__ float s_[];
    float* Phi = s_;                // [qi][kj]
    float* Plo = s_ + ATT_T;
    float* Vhi = s_ + 2 * ATT_T;    // [d][kj] (V transposed)
    float* Vlo = s_ + 3 * ATT_T;
    int z = blockIdx.y;
    int b = z / NH, h = z % NH;
    int qi0 = blockIdx.x * 64;
    int tid = threadIdx.x;
    int fr = tid >> 4, fc4 = (tid & 15) * 4;
    int w = tid >> 5, lane = tid & 31;
    int g = lane >> 2, t = lane & 3;
    int warp_m = (w & 1) * 32, warp_n = (w >> 1) * 16;
    const float* sbase = g_scores + (size_t)z * NTOK * SCR;
    const float* vbase = g_qkv + (size_t)b * NTOK * QKVW + 2 * DIM + h * HD;
    const uint32_t* ph = (const uint32_t*)Phi;
    const uint32_t* pl = (const uint32_t*)Plo;
    const uint32_t* vh = (const uint32_t*)Vhi;
    const uint32_t* vl = (const uint32_t*)Vlo;

    float acc[2][2][4] = {};
    for (int kt = 0; kt < 10; kt++) {
        int kj0 = kt * 64;
#pragma unroll
        for (int rr = 0; rr < 64; rr += 16) {
            int qi = qi0 + fr + rr;
            float4 pv = make_float4(0.f, 0.f, 0.f, 0.f);
            if (qi < NTOK) {
                pv = *(const float4*)(sbase + (size_t)qi * SCR + kj0 + fc4);
                if (kj0 + fc4 + 3 >= NTOK) {   // mask padded columns
                    if (kj0 + fc4 + 0 >= NTOK) pv.x = 0.f;
                    if (kj0 + fc4 + 1 >= NTOK) pv.y = 0.f;
                    if (kj0 + fc4 + 2 >= NTOK) pv.z = 0.f;
                    if (kj0 + fc4 + 3 >= NTOK) pv.w = 0.f;
                }
            }
            float4 hi, lo;
            split4(pv, hi, lo);
            *(float4*)&Phi[(fr + rr) * 68 + fc4] = hi;
            *(float4*)&Plo[(fr + rr) * 68 + fc4] = lo;
            int kn = kj0 + fr + rr;
            float4 vv = make_float4(0.f, 0.f, 0.f, 0.f);
            if (kn < NTOK) vv = *(const float4*)(vbase + (size_t)kn * QKVW + fc4);
            split4(vv, hi, lo);
            Vhi[(fc4 + 0) * 68 + fr + rr] = hi.x;
            Vhi[(fc4 + 1) * 68 + fr + rr] = hi.y;
            Vhi[(fc4 + 2) * 68 + fr + rr] = hi.z;
            Vhi[(fc4 + 3) * 68 + fr + rr] = hi.w;
            Vlo[(fc4 + 0) * 68 + fr + rr] = lo.x;
            Vlo[(fc4 + 1) * 68 + fr + rr] = lo.y;
            Vlo[(fc4 + 2) * 68 + fr + rr] = lo.z;
            Vlo[(fc4 + 3) * 68 + fr + rr] = lo.w;
        }
        __syncthreads();
#pragma unroll
        for (int ks = 0; ks < 8; ks++) {
            int k0 = ks * 8;
            uint32_t ah[2][4], al[2][4], bh[2][2], bl[2][2];
#pragma unroll
            for (int mt = 0; mt < 2; mt++) {
                int rb = (warp_m + mt * 16 + g) * 68 + k0 + t;
                ah[mt][0] = ph[rb]; ah[mt][1] = ph[rb + 8 * 68];
                ah[mt][2] = ph[rb + 4]; ah[mt][3] = ph[rb + 8 * 68 + 4];
                al[mt][0] = pl[rb]; al[mt][1] = pl[rb + 8 * 68];
                al[mt][2] = pl[rb + 4]; al[mt][3] = pl[rb + 8 * 68 + 4];
            }
#pragma unroll
            for (int nt = 0; nt < 2; nt++) {
                int rb = (warp_n + nt * 8 + g) * 68 + k0 + t;
                bh[nt][0] = vh[rb]; bh[nt][1] = vh[rb + 4];
                bl[nt][0] = vl[rb]; bl[nt][1] = vl[rb + 4];
            }
#pragma unroll
            for (int mt = 0; mt < 2; mt++)
#pragma unroll
                for (int nt = 0; nt < 2; nt++) {
                    mma_tf32(acc[mt][nt], ah[mt], bh[nt]);
                    mma_tf32(acc[mt][nt], ah[mt], bl[nt]);
                    mma_tf32(acc[mt][nt], al[mt], bh[nt]);
                }
        }
        __syncthreads();
    }
#pragma unroll
    for (int mt = 0; mt < 2; mt++)
#pragma unroll
        for (int half = 0; half < 2; half++) {
            int qi = qi0 + warp_m + mt * 16 + g + half * 8;
            if (qi >= NTOK) continue;
            float* orow = g_o + ((size_t)b * NTOK + qi) * DIM + h * HD;
#pragma unroll
            for (int nt = 0; nt < 2; nt++) {
                int col = warp_n + nt * 8 + 2 * t;
                *(float2*)&orow[col] = make_float2(acc[mt][nt][half * 2],
                                                   acc[mt][nt][half * 2 + 1]);
            }
        }
}

// ---------------- patch embed helpers --------------------------------------
__global__ void extract_patches_kernel(const float* __restrict__ x) {
    int idx = blockIdx.x * blockDim.x + threadIdx.x;
    if (idx >= BATCH * NPATCH * DIM) return;
    int f = idx % DIM;
    int p = (idx / DIM) % NPATCH;
    int b = idx / (DIM * NPATCH);
    int gy = p / 24, gx = p % 24;
    int c = f >> 8;
    int rem = f & 255;
    int py = rem >> 4, px = rem & 15;
    g_patches[idx] = x[(((size_t)b * 3 + c) * 384 + gy * 16 + py) * 384 + gx * 16 + px];
}

__global__ void embed_kernel(const float* __restrict__ cls, const float* __restrict__ pos) {
    int idx = blockIdx.x * blockDim.x + threadIdx.x;
    if (idx >= ROWS * DIM) return;
    int d = idx % DIM;
    int t = (idx / DIM) % NTOK;
    int b = idx / (DIM * NTOK);
    float v = (t == 0) ? cls[d] : g_tmp[((size_t)b * NPATCH + (t - 1)) * DIM + d];
    g_h[idx] = v + pos[t * DIM + d];
}

// ---------------- classification head --------------------------------------
__global__ void head_kernel(const float* __restrict__ hw, const float* __restrict__ hb,
                            float* __restrict__ out) {
    __shared__ float xs[DIM];
    int b = blockIdx.y;
    int tid = threadIdx.x;
    const float* xr = g_cls + b * DIM;
    xs[tid] = xr[tid];
    xs[tid + 256] = xr[tid + 256];
    xs[tid + 512] = xr[tid + 512];
    __syncthreads();
    int c = blockIdx.x * 256 + tid;
    if (c < NCLS) {
        float acc = hb[c];
        for (int d = 0; d < DIM; d++)
            acc = fmaf(xs[d], hw[(size_t)d * NCLS + c], acc);
        out[b * NCLS + c] = acc;
    }
}

// ---------------- launch ----------------------------------------------------
extern "C" void kernel_launch(void* const* d_in, const int* in_sizes, int n_in,
                              void* d_out, int out_size) {
    const float* x       = (const float*)d_in[0];
    const float* patch_w = (const float*)d_in[1];
    const float* patch_b = (const float*)d_in[2];
    const float* cls_tok = (const float*)d_in[3];
    const float* pos_emb = (const float*)d_in[4];
    const float* ln1_g   = (const float*)d_in[5];
    const float* ln1_b   = (const float*)d_in[6];
    const float* qkv_w   = (const float*)d_in[7];
    const float* qkv_b   = (const float*)d_in[8];
    const float* proj_w  = (const float*)d_in[9];
    const float* proj_b  = (const float*)d_in[10];
    const float* ln2_g   = (const float*)d_in[11];
    const float* ln2_b   = (const float*)d_in[12];
    const float* mlp_w1  = (const float*)d_in[13];
    const float* mlp_b1  = (const float*)d_in[14];
    const float* mlp_w2  = (const float*)d_in[15];
    const float* mlp_b2  = (const float*)d_in[16];
    const float* lnf_g   = (const float*)d_in[17];
    const float* lnf_b   = (const float*)d_in[18];
    const float* head_w  = (const float*)d_in[19];
    const float* head_b  = (const float*)d_in[20];
    float* out = (float*)d_out;

    float *h_, *qkv_, *o_, *mid_, *pat_, *tmp_;
    float *qkvT_, *projT_, *w1T_, *w2T_;
    cudaGetSymbolAddress((void**)&h_, g_h);
    cudaGetSymbolAddress((void**)&qkv_, g_qkv);
    cudaGetSymbolAddress((void**)&o_, g_o);
    cudaGetSymbolAddress((void**)&mid_, g_mid);
    cudaGetSymbolAddress((void**)&pat_, g_patches);
    cudaGetSymbolAddress((void**)&tmp_, g_tmp);
    cudaGetSymbolAddress((void**)&qkvT_, g_qkvT);
    cudaGetSymbolAddress((void**)&projT_, g_projT);
    cudaGetSymbolAddress((void**)&w1T_, g_w1T);
    cudaGetSymbolAddress((void**)&w2T_, g_w2T);

    cudaFuncSetAttribute(gemm_mma<0, false>, cudaFuncAttributeMaxDynamicSharedMemorySize, GEMM_SMEM);
    cudaFuncSetAttribute(gemm_mma<0, true>,  cudaFuncAttributeMaxDynamicSharedMemorySize, GEMM_SMEM);
    cudaFuncSetAttribute(gemm_mma<1, true>,  cudaFuncAttributeMaxDynamicSharedMemorySize, GEMM_SMEM);
    cudaFuncSetAttribute(gemm_mma<2, false>, cudaFuncAttributeMaxDynamicSharedMemorySize, GEMM_SMEM);
    cudaFuncSetAttribute(attn_scores_mma,    cudaFuncAttributeMaxDynamicSharedMemorySize, ATT_SMEM);
    cudaFuncSetAttribute(attn_out_mma,       cudaFuncAttributeMaxDynamicSharedMemorySize, ATT_SMEM);

    dim3 tb(32, 8);
    transpose_kernel<<<dim3(QKVW / 32, DIM / 32, DEPTH), tb>>>(qkv_w, qkvT_, DIM, QKVW);
    transpose_kernel<<<dim3(DIM / 32, DIM / 32, DEPTH), tb>>>(proj_w, projT_, DIM, DIM);
    transpose_kernel<<<dim3(HID / 32, DIM / 32, DEPTH), tb>>>(mlp_w1, w1T_, DIM, HID);
    transpose_kernel<<<dim3(DIM / 32, HID / 32, DEPTH), tb>>>(mlp_w2, w2T_, HID, DIM);

    extract_patches_kernel<<<(BATCH * NPATCH * DIM + 255) / 256, 256>>>(x);
    gemm_mma<0, false><<<dim3(DIM / 128, (BATCH * NPATCH) / 128), 256, GEMM_SMEM>>>(
        pat_, patch_w, patch_b, nullptr, nullptr, nullptr, tmp_, BATCH * NPATCH, DIM, DIM);
    embed_kernel<<<(ROWS * DIM + 255) / 256, 256>>>(cls_tok, pos_emb);

    const int MG = (ROWS + 127) / 128;  // 37

    for (int l = 0; l < DEPTH; l++) {
        ln_stats_kernel<<<ROWS, 256>>>(h_, 1e-5f);
        gemm_mma<0, true><<<dim3(QKVW / 128, MG), 256, GEMM_SMEM>>>(
            h_, qkvT_ + (size_t)l * QKVW * DIM, qkv_b + (size_t)l * QKVW,
            nullptr, ln1_g + l * DIM, ln1_b + l * DIM, qkv_, ROWS, QKVW, DIM);
        attn_scores_mma<<<dim3(10, 10, BATCH * NH), 256, ATT_SMEM>>>();
        softmax_kernel<<<dim3(NTOK, BATCH * NH), 256>>>();
        attn_out_mma<<<dim3(10, BATCH * NH), 256, ATT_SMEM>>>();
        gemm_mma<2, false><<<dim3(DIM / 128, MG), 256, GEMM_SMEM>>>(
            o_, projT_ + (size_t)l * DIM * DIM, proj_b + (size_t)l * DIM,
            h_, nullptr, nullptr, h_, ROWS, DIM, DIM);
        ln_stats_kernel<<<ROWS, 256>>>(h_, 1e-5f);
        gemm_mma<1, true><<<dim3(HID / 128, MG), 256, GEMM_SMEM>>>(
            h_, w1T_ + (size_t)l * HID * DIM, mlp_b1 + (size_t)l * HID,
            nullptr, ln2_g + l * DIM, ln2_b + l * DIM, mid_, ROWS, HID, DIM);
        gemm_mma<2, false><<<dim3(DIM / 128, MG), 256, GEMM_SMEM>>>(
            mid_, w2T_ + (size_t)l * DIM * HID, mlp_b2 + (size_t)l * DIM,
            h_, nullptr, nullptr, h_, ROWS, DIM, HID);
    }

    ln_cls_kernel<<<BATCH, 256>>>(lnf_g, lnf_b, 1e-6f);
    head_kernel<<<dim3(4, BATCH), 256>>>(head_w, head_b, out);
}

// round 13
// speedup vs baseline: 1.1169x; 1.1169x over previous
#include <cuda_runtime.h>
#include <cstdint>
#include <math.h>

#define DEPTH 12
#define DIM   768
#define NH    12
#define HD    64
#define NTOK  577
#define BATCH 8
#define HID   3072
#define NCLS  1000
#define NPATCH 576
#define ROWS  (BATCH * NTOK)      // 4616
#define QKVW  (3 * DIM)           // 2304

// ---------------- scratch (device globals; allocation-free) ----------------
__device__ float g_h[ROWS * DIM];
__device__ float g_y[ROWS * DIM];
__device__ float g_qkv[ROWS * QKVW];
__device__ float g_scores[BATCH * NH * NTOK * NTOK];
__device__ float g_o[ROWS * DIM];
__device__ float g_mid[ROWS * HID];
__device__ float g_patches[BATCH * NPATCH * DIM];
__device__ float g_tmp[BATCH * NPATCH * DIM];
__device__ float g_cls[BATCH * DIM];
__device__ float g_qkvT[DEPTH * QKVW * DIM];
__device__ float g_projT[DEPTH * DIM * DIM];
__device__ float g_w1T[DEPTH * HID * DIM];
__device__ float g_w2T[DEPTH * DIM * HID];

// ====================== helpers ============================================
__device__ __forceinline__ uint32_t smem_u32(const void* p) {
    uint32_t a;
    asm("{ .reg .u64 t; cvta.to.shared.u64 t, %1; cvt.u32.u64 %0, t; }" : "=r"(a) : "l"(p));
    return a;
}
#define CP_ASYNC16(dst, src, sz) \
    asm volatile("cp.async.cg.shared.global [%0], [%1], 16, %2;" \
                 :: "r"(dst), "l"(src), "r"(sz))
#define CP_COMMIT() asm volatile("cp.async.commit_group;" ::: "memory")
#define CP_WAIT1()  asm volatile("cp.async.wait_group 1;" ::: "memory")
#define CP_WAIT0()  asm volatile("cp.async.wait_group 0;" ::: "memory")

__device__ __forceinline__ uint32_t cvt_tf32(float f) {
    uint32_t u;
    asm("cvt.rna.tf32.f32 %0, %1;" : "=r"(u) : "f"(f));
    return u;
}

__device__ __forceinline__ void mma_tf32(float* c, const uint32_t* a, const uint32_t* b) {
    asm volatile(
        "mma.sync.aligned.m16n8k8.row.col.f32.tf32.tf32.f32 "
        "{%0,%1,%2,%3}, {%4,%5,%6,%7}, {%8,%9}, {%0,%1,%2,%3};"
        : "+f"(c[0]), "+f"(c[1]), "+f"(c[2]), "+f"(c[3])
        : "r"(a[0]), "r"(a[1]), "r"(a[2]), "r"(a[3]), "r"(b[0]), "r"(b[1]));
}

// ====================== tf32 mma.sync dense GEMM (cp.async) ================
// C[M,N] = A[M,K] @ BT[N,K]^T + bias (+epi). 128x128 tile, K-chunk 32,
// 8 warps (64m x 32n each), double-buffered via cp.async groups.
// fp32 stored raw in smem; cvt.rna applied at fragment load (bitwise same
// operands as cvt-at-store). EPI: 0=bias, 1=bias+GELU, 2=bias+residual.
#define SMS 36
#define TILE_F (128 * SMS)
#define GEMM_SMEM (4 * TILE_F * 4)  // 73728 B

__device__ __forceinline__ void prefetch_chunk(const float* __restrict__ A,
                                               const float* __restrict__ BT,
                                               int M, int K, int row0, int col0,
                                               int k0, uint32_t sA, uint32_t sB, int tid) {
#pragma unroll
    for (int i = 0; i < 4; i++) {
        int f4 = tid + i * 256;
        int r = f4 >> 3, cc = (f4 & 7) * 4;
        int gr = row0 + r;
        const float* ga = A + (size_t)(gr < M ? gr : 0) * K + k0 + cc;
        CP_ASYNC16(sA + (uint32_t)(r * SMS + cc) * 4, ga, (gr < M) ? 16 : 0);
        const float* gb = BT + (size_t)(col0 + r) * K + k0 + cc;
        CP_ASYNC16(sB + (uint32_t)(r * SMS + cc) * 4, gb, 16);
    }
}

template <int EPI>
__global__ void __launch_bounds__(256, 2)
gemm_mma(const float* __restrict__ A, const float* __restrict__ BT,
         const float* __restrict__ bias, const float* __restrict__ res,
         float* __restrict__ C, int M, int N, int K) {
    extern __shared__ float sm[];
    uint32_t sbase = smem_u32(sm);
    const int tid = threadIdx.x;
    const int w = tid >> 5, lane = tid & 31;
    const int g = lane >> 2, t = lane & 3;
    const int warp_m = (w & 1) * 64, warp_n = (w >> 1) * 32;
    const int row0 = blockIdx.y * 128, col0 = blockIdx.x * 128;

    float acc[4][4][4] = {};
    const int NC = K / 32;

    // smem: As[2] at 0 / TILE_F, Bs[2] at 2*TILE_F / 3*TILE_F (floats)
    prefetch_chunk(A, BT, M, K, row0, col0, 0,
                   sbase, sbase + 2 * TILE_F * 4, tid);
    CP_COMMIT();

    for (int ch = 0; ch < NC; ch++) {
        int buf = ch & 1;
        if (ch + 1 < NC) {
            int nb = buf ^ 1;
            prefetch_chunk(A, BT, M, K, row0, col0, (ch + 1) * 32,
                           sbase + nb * TILE_F * 4,
                           sbase + (2 + nb) * TILE_F * 4, tid);
            CP_COMMIT();
            CP_WAIT1();     // chunk ch's group complete
        } else {
            CP_WAIT0();
        }
        __syncthreads();

        const float* fA = sm + buf * TILE_F;
        const float* fB = sm + (2 + buf) * TILE_F;
#pragma unroll
        for (int ks = 0; ks < 4; ks++) {
            int k0 = ks * 8;
            uint32_t a[4][4], b[4][2];
#pragma unroll
            for (int mt = 0; mt < 4; mt++) {
                int rb = (warp_m + mt * 16 + g) * SMS + k0 + t;
                a[mt][0] = cvt_tf32(fA[rb]);
                a[mt][1] = cvt_tf32(fA[rb + 8 * SMS]);
                a[mt][2] = cvt_tf32(fA[rb + 4]);
                a[mt][3] = cvt_tf32(fA[rb + 8 * SMS + 4]);
            }
#pragma unroll
            for (int nt = 0; nt < 4; nt++) {
                int rb = (warp_n + nt * 8 + g) * SMS + k0 + t;
                b[nt][0] = cvt_tf32(fB[rb]);
                b[nt][1] = cvt_tf32(fB[rb + 4]);
            }
#pragma unroll
            for (int mt = 0; mt < 4; mt++)
#pragma unroll
                for (int nt = 0; nt < 4; nt++)
                    mma_tf32(acc[mt][nt], a[mt], b[nt]);
        }
        __syncthreads();   // all warps done with buf before it is re-filled
    }

#pragma unroll
    for (int mt = 0; mt < 4; mt++) {
#pragma unroll
        for (int half = 0; half < 2; half++) {
            int r = row0 + warp_m + mt * 16 + g + half * 8;
            if (r >= M) continue;
            float* crow = C + (size_t)r * N;
            const float* rrow = (EPI == 2) ? res + (size_t)r * N : nullptr;
#pragma unroll
            for (int nt = 0; nt < 4; nt++) {
                int col = col0 + warp_n + nt * 8 + 2 * t;
                float v0 = acc[mt][nt][half * 2 + 0] + bias[col];
                float v1 = acc[mt][nt][half * 2 + 1] + bias[col + 1];
                if (EPI == 1) {
                    v0 = 0.5f * v0 * (1.f + erff(v0 * 0.70710678118654752f));
                    v1 = 0.5f * v1 * (1.f + erff(v1 * 0.70710678118654752f));
                }
                if (EPI == 2) {
                    v0 += rrow[col];
                    v1 += rrow[col + 1];
                }
                *(float2*)&crow[col] = make_float2(v0, v1);
            }
        }
    }
}

// ---------------- weight transpose: src[K][N] -> dst[N][K] -----------------
__global__ void transpose_kernel(const float* __restrict__ src, float* __restrict__ dst,
                                 int K, int N) {
    __shared__ float t[32][33];
    const float* s = src + (size_t)blockIdx.z * K * N;
    float* d = dst + (size_t)blockIdx.z * K * N;
    int k0 = blockIdx.y * 32, n0 = blockIdx.x * 32;
    int x = threadIdx.x, y = threadIdx.y;  // 32 x 8
#pragma unroll
    for (int i = 0; i < 32; i += 8)
        t[y + i][x] = s[(size_t)(k0 + y + i) * N + n0 + x];
    __syncthreads();
#pragma unroll
    for (int i = 0; i < 32; i += 8)
        d[(size_t)(n0 + y + i) * K + k0 + x] = t[x][y + i];
}

// ---------------- LayerNorm over last dim (768), one block per row ---------
__global__ void ln_kernel(const float* __restrict__ x, const float* __restrict__ g,
                          const float* __restrict__ b, float* __restrict__ y, float eps) {
    int row = blockIdx.x;
    const float* xr = x + (size_t)row * DIM;
    float* yr = y + (size_t)row * DIM;
    int tid = threadIdx.x;
    float v0 = xr[tid], v1 = xr[tid + 256], v2 = xr[tid + 512];
    float s = v0 + v1 + v2;
    float sq = v0 * v0 + v1 * v1 + v2 * v2;
#pragma unroll
    for (int o = 16; o; o >>= 1) {
        s  += __shfl_xor_sync(0xffffffffu, s, o);
        sq += __shfl_xor_sync(0xffffffffu, sq, o);
    }
    __shared__ float ss[8], ssq[8], red[2];
    int w = tid >> 5, l = tid & 31;
    if (l == 0) { ss[w] = s; ssq[w] = sq; }
    __syncthreads();
    if (tid == 0) {
        float ts = 0.f, tq = 0.f;
        for (int i = 0; i < 8; i++) { ts += ss[i]; tq += ssq[i]; }
        float m = ts * (1.f / DIM);
        float var = tq * (1.f / DIM) - m * m;
        red[0] = m;
        red[1] = rsqrtf(var + eps);
    }
    __syncthreads();
    float m = red[0], r = red[1];
    yr[tid]       = (v0 - m) * r * g[tid]       + b[tid];
    yr[tid + 256] = (v1 - m) * r * g[tid + 256] + b[tid + 256];
    yr[tid + 512] = (v2 - m) * r * g[tid + 512] + b[tid + 512];
}

// ---------------- final LN (cls rows only) ---------------------------------
__global__ void ln_cls_kernel(const float* __restrict__ g, const float* __restrict__ b,
                              float eps) {
    int bb = blockIdx.x;
    const float* xr = g_h + (size_t)bb * NTOK * DIM;  // token 0
    int tid = threadIdx.x;
    float v0 = xr[tid], v1 = xr[tid + 256], v2 = xr[tid + 512];
    float s = v0 + v1 + v2;
    float sq = v0 * v0 + v1 * v1 + v2 * v2;
#pragma unroll
    for (int o = 16; o; o >>= 1) {
        s  += __shfl_xor_sync(0xffffffffu, s, o);
        sq += __shfl_xor_sync(0xffffffffu, sq, o);
    }
    __shared__ float ss[8], ssq[8], red[2];
    int w = tid >> 5, l = tid & 31;
    if (l == 0) { ss[w] = s; ssq[w] = sq; }
    __syncthreads();
    if (tid == 0) {
        float ts = 0.f, tq = 0.f;
        for (int i = 0; i < 8; i++) { ts += ss[i]; tq += ssq[i]; }
        float m = ts * (1.f / DIM);
        float var = tq * (1.f / DIM) - m * m;
        red[0] = m;
        red[1] = rsqrtf(var + eps);
    }
    __syncthreads();
    float m = red[0], r = red[1];
    float* yr = g_cls + bb * DIM;
    yr[tid]       = (v0 - m) * r * g[tid]       + b[tid];
    yr[tid + 256] = (v1 - m) * r * g[tid + 256] + b[tid + 256];
    yr[tid + 512] = (v2 - m) * r * g[tid + 512] + b[tid + 512];
}

// ---------------- attention: scores = (Q @ K^T) * 1/8 ----------------------
__global__ void attn_scores_kernel() {
    int z = blockIdx.z;
    int b = z / NH, h = z % NH;
    int qi0 = blockIdx.y * 64, kj0 = blockIdx.x * 64;
    __shared__ float qs[64][68];
    __shared__ float kst[64][68];
    int tid = threadIdx.x;
    int fr = tid >> 4, fc4 = (tid & 15) * 4;
    const float* qbase = g_qkv + (size_t)b * NTOK * QKVW + h * HD;
    const float* kbase = qbase + DIM;
#pragma unroll
    for (int rr = 0; rr < 64; rr += 16) {
        int qn = qi0 + fr + rr;
        float4 v = make_float4(0.f, 0.f, 0.f, 0.f);
        if (qn < NTOK) v = *(const float4*)(qbase + (size_t)qn * QKVW + fc4);
        *(float4*)&qs[fr + rr][fc4] = v;
        int kn = kj0 + fr + rr;
        float4 w = make_float4(0.f, 0.f, 0.f, 0.f);
        if (kn < NTOK) w = *(const float4*)(kbase + (size_t)kn * QKVW + fc4);
        kst[fc4 + 0][fr + rr] = w.x;
        kst[fc4 + 1][fr + rr] = w.y;
        kst[fc4 + 2][fr + rr] = w.z;
        kst[fc4 + 3][fr + rr] = w.w;
    }
    __syncthreads();
    int ty = tid >> 4, tx = tid & 15;
    float acc[4][4] = {};
#pragma unroll
    for (int d = 0; d < 64; d++) {
        float a[4], c[4];
#pragma unroll
        for (int i = 0; i < 4; i++) a[i] = qs[ty * 4 + i][d];
#pragma unroll
        for (int j = 0; j < 4; j++) c[j] = kst[d][tx * 4 + j];
#pragma unroll
        for (int i = 0; i < 4; i++)
#pragma unroll
            for (int j = 0; j < 4; j++)
                acc[i][j] = fmaf(a[i], c[j], acc[i][j]);
    }
    float* sbuf = g_scores + (size_t)z * NTOK * NTOK;
#pragma unroll
    for (int i = 0; i < 4; i++) {
        int qi = qi0 + ty * 4 + i;
        if (qi >= NTOK) continue;
#pragma unroll
        for (int j = 0; j < 4; j++) {
            int kj = kj0 + tx * 4 + j;
            if (kj < NTOK) sbuf[(size_t)qi * NTOK + kj] = acc[i][j] * 0.125f;
        }
    }
}

// ---------------- softmax over rows of 577 ---------------------------------
__global__ void softmax_kernel() {
    size_t row = blockIdx.x;
    float* p = g_scores + row * NTOK;
    int tid = threadIdx.x;
    float v[3];
    float mx = -1e30f;
#pragma unroll
    for (int i = 0; i < 3; i++) {
        int idx = tid + i * 256;
        v[i] = (idx < NTOK) ? p[idx] : -1e30f;
        mx = fmaxf(mx, v[i]);
    }
#pragma unroll
    for (int o = 16; o; o >>= 1) mx = fmaxf(mx, __shfl_xor_sync(0xffffffffu, mx, o));
    __shared__ float sm_[8], sred[2];
    int w = tid >> 5, l = tid & 31;
    if (l == 0) sm_[w] = mx;
    __syncthreads();
    if (tid == 0) {
        float tt = sm_[0];
        for (int i = 1; i < 8; i++) tt = fmaxf(tt, sm_[i]);
        sred[0] = tt;
    }
    __syncthreads();
    mx = sred[0];
    float sum = 0.f;
#pragma unroll
    for (int i = 0; i < 3; i++) {
        int idx = tid + i * 256;
        if (idx < NTOK) { v[i] = expf(v[i] - mx); sum += v[i]; }
    }
#pragma unroll
    for (int o = 16; o; o >>= 1) sum += __shfl_xor_sync(0xffffffffu, sum, o);
    __syncthreads();
    if (l == 0) sm_[w] = sum;
    __syncthreads();
    if (tid == 0) {
        float tt = 0.f;
        for (int i = 0; i < 8; i++) tt += sm_[i];
        sred[1] = 1.f / tt;
    }
    __syncthreads();
    float inv = sred[1];
#pragma unroll
    for (int i = 0; i < 3; i++) {
        int idx = tid + i * 256;
        if (idx < NTOK) p[idx] = v[i] * inv;
    }
}

// ---------------- attention: O = att @ V -----------------------------------
__global__ void attn_out_kernel() {
    int z = blockIdx.y;
    int b = z / NH, h = z % NH;
    int qi0 = blockIdx.x * 64;
    __shared__ float att_s[64][68];
    __shared__ float v_s[64][68];
    int tid = threadIdx.x;
    int ty = tid >> 4, tx = tid & 15;
    int fr = tid >> 4, fc4 = (tid & 15) * 4;
    float acc[4][4] = {};
    const float* sbase = g_scores + (size_t)z * NTOK * NTOK;
    const float* vbase = g_qkv + (size_t)b * NTOK * QKVW + 2 * DIM + h * HD;
    for (int kt = 0; kt < 10; kt++) {
        int kj0 = kt * 64;
#pragma unroll
        for (int rr = 0; rr < 64; rr += 16) {
            int qi = qi0 + fr + rr;
#pragma unroll
            for (int u = 0; u < 4; u++) {
                int kj = kj0 + fc4 + u;
                att_s[fr + rr][fc4 + u] =
                    (qi < NTOK && kj < NTOK) ? sbase[(size_t)qi * NTOK + kj] : 0.f;
            }
            int kn = kj0 + fr + rr;
            float4 w = make_float4(0.f, 0.f, 0.f, 0.f);
            if (kn < NTOK) w = *(const float4*)(vbase + (size_t)kn * QKVW + fc4);
            *(float4*)&v_s[fr + rr][fc4] = w;
        }
        __syncthreads();
#pragma unroll
        for (int kj = 0; kj < 64; kj++) {
            float a[4], c[4];
#pragma unroll
            for (int i = 0; i < 4; i++) a[i] = att_s[ty * 4 + i][kj];
#pragma unroll
            for (int j = 0; j < 4; j++) c[j] = v_s[kj][tx * 4 + j];
#pragma unroll
            for (int i = 0; i < 4; i++)
#pragma unroll
                for (int j = 0; j < 4; j++)
                    acc[i][j] = fmaf(a[i], c[j], acc[i][j]);
        }
        __syncthreads();
    }
#pragma unroll
    for (int i = 0; i < 4; i++) {
        int qi = qi0 + ty * 4 + i;
        if (qi >= NTOK) continue;
        float* orow = g_o + ((size_t)b * NTOK + qi) * DIM + h * HD;
#pragma unroll
        for (int j = 0; j < 4; j++) orow[tx * 4 + j] = acc[i][j];
    }
}

// ---------------- patch embed helpers --------------------------------------
__global__ void extract_patches_kernel(const float* __restrict__ x) {
    int idx = blockIdx.x * blockDim.x + threadIdx.x;
    if (idx >= BATCH * NPATCH * DIM) return;
    int f = idx % DIM;
    int p = (idx / DIM) % NPATCH;
    int b = idx / (DIM * NPATCH);
    int gy = p / 24, gx = p % 24;
    int c = f >> 8;
    int rem = f & 255;
    int py = rem >> 4, px = rem & 15;
    g_patches[idx] = x[(((size_t)b * 3 + c) * 384 + gy * 16 + py) * 384 + gx * 16 + px];
}

__global__ void embed_kernel(const float* __restrict__ cls, const float* __restrict__ pos) {
    int idx = blockIdx.x * blockDim.x + threadIdx.x;
    if (idx >= ROWS * DIM) return;
    int d = idx % DIM;
    int t = (idx / DIM) % NTOK;
    int b = idx / (DIM * NTOK);
    float v = (t == 0) ? cls[d] : g_tmp[((size_t)b * NPATCH + (t - 1)) * DIM + d];
    g_h[idx] = v + pos[t * DIM + d];
}

// ---------------- classification head --------------------------------------
__global__ void head_kernel(const float* __restrict__ hw, const float* __restrict__ hb,
                            float* __restrict__ out) {
    __shared__ float xs[DIM];
    int b = blockIdx.y;
    int tid = threadIdx.x;
    const float* xr = g_cls + b * DIM;
    xs[tid] = xr[tid];
    xs[tid + 256] = xr[tid + 256];
    xs[tid + 512] = xr[tid + 512];
    __syncthreads();
    int c = blockIdx.x * 256 + tid;
    if (c < NCLS) {
        float acc = hb[c];
        for (int d = 0; d < DIM; d++)
            acc = fmaf(xs[d], hw[(size_t)d * NCLS + c], acc);
        out[b * NCLS + c] = acc;
    }
}

// ---------------- launch ----------------------------------------------------
extern "C" void kernel_launch(void* const* d_in, const int* in_sizes, int n_in,
                              void* d_out, int out_size) {
    const float* x       = (const float*)d_in[0];
    const float* patch_w = (const float*)d_in[1];
    const float* patch_b = (const float*)d_in[2];
    const float* cls_tok = (const float*)d_in[3];
    const float* pos_emb = (const float*)d_in[4];
    const float* ln1_g   = (const float*)d_in[5];
    const float* ln1_b   = (const float*)d_in[6];
    const float* qkv_w   = (const float*)d_in[7];
    const float* qkv_b   = (const float*)d_in[8];
    const float* proj_w  = (const float*)d_in[9];
    const float* proj_b  = (const float*)d_in[10];
    const float* ln2_g   = (const float*)d_in[11];
    const float* ln2_b   = (const float*)d_in[12];
    const float* mlp_w1  = (const float*)d_in[13];
    const float* mlp_b1  = (const float*)d_in[14];
    const float* mlp_w2  = (const float*)d_in[15];
    const float* mlp_b2  = (const float*)d_in[16];
    const float* lnf_g   = (const float*)d_in[17];
    const float* lnf_b   = (const float*)d_in[18];
    const float* head_w  = (const float*)d_in[19];
    const float* head_b  = (const float*)d_in[20];
    float* out = (float*)d_out;

    float *h_, *y_, *qkv_, *o_, *mid_, *pat_, *tmp_;
    float *qkvT_, *projT_, *w1T_, *w2T_;
    cudaGetSymbolAddress((void**)&h_, g_h);
    cudaGetSymbolAddress((void**)&y_, g_y);
    cudaGetSymbolAddress((void**)&qkv_, g_qkv);
    cudaGetSymbolAddress((void**)&o_, g_o);
    cudaGetSymbolAddress((void**)&mid_, g_mid);
    cudaGetSymbolAddress((void**)&pat_, g_patches);
    cudaGetSymbolAddress((void**)&tmp_, g_tmp);
    cudaGetSymbolAddress((void**)&qkvT_, g_qkvT);
    cudaGetSymbolAddress((void**)&projT_, g_projT);
    cudaGetSymbolAddress((void**)&w1T_, g_w1T);
    cudaGetSymbolAddress((void**)&w2T_, g_w2T);

    cudaFuncSetAttribute(gemm_mma<0>, cudaFuncAttributeMaxDynamicSharedMemorySize, GEMM_SMEM);
    cudaFuncSetAttribute(gemm_mma<1>, cudaFuncAttributeMaxDynamicSharedMemorySize, GEMM_SMEM);
    cudaFuncSetAttribute(gemm_mma<2>, cudaFuncAttributeMaxDynamicSharedMemorySize, GEMM_SMEM);

    // Weight transposes ([K][N] -> [N][K]) once per launch
    dim3 tb(32, 8);
    transpose_kernel<<<dim3(QKVW / 32, DIM / 32, DEPTH), tb>>>(qkv_w, qkvT_, DIM, QKVW);
    transpose_kernel<<<dim3(DIM / 32, DIM / 32, DEPTH), tb>>>(proj_w, projT_, DIM, DIM);
    transpose_kernel<<<dim3(HID / 32, DIM / 32, DEPTH), tb>>>(mlp_w1, w1T_, DIM, HID);
    transpose_kernel<<<dim3(DIM / 32, HID / 32, DEPTH), tb>>>(mlp_w2, w2T_, HID, DIM);

    // Patch embedding: patch_w is [DIM][768] = [N][K] K-major already
    extract_patches_kernel<<<(BATCH * NPATCH * DIM + 255) / 256, 256>>>(x);
    gemm_mma<0><<<dim3(DIM / 128, (BATCH * NPATCH) / 128), 256, GEMM_SMEM>>>(
        pat_, patch_w, patch_b, nullptr, tmp_, BATCH * NPATCH, DIM, DIM);
    embed_kernel<<<(ROWS * DIM + 255) / 256, 256>>>(cls_tok, pos_emb);

    const int MG = (ROWS + 127) / 128;  // 37

    for (int l = 0; l < DEPTH; l++) {
        ln_kernel<<<ROWS, 256>>>(h_, ln1_g + l * DIM, ln1_b + l * DIM, y_, 1e-5f);
        gemm_mma<0><<<dim3(QKVW / 128, MG), 256, GEMM_SMEM>>>(
            y_, qkvT_ + (size_t)l * QKVW * DIM, qkv_b + (size_t)l * QKVW,
            nullptr, qkv_, ROWS, QKVW, DIM);
        attn_scores_kernel<<<dim3(10, 10, BATCH * NH), 256>>>();
        softmax_kernel<<<BATCH * NH * NTOK, 256>>>();
        attn_out_kernel<<<dim3(10, BATCH * NH), 256>>>();
        gemm_mma<2><<<dim3(DIM / 128, MG), 256, GEMM_SMEM>>>(
            o_, projT_ + (size_t)l * DIM * DIM, proj_b + (size_t)l * DIM,
            h_, h_, ROWS, DIM, DIM);
        ln_kernel<<<ROWS, 256>>>(h_, ln2_g + l * DIM, ln2_b + l * DIM, y_, 1e-5f);
        gemm_mma<1><<<dim3(HID / 128, MG), 256, GEMM_SMEM>>>(
            y_, w1T_ + (size_t)l * HID * DIM, mlp_b1 + (size_t)l * HID,
            nullptr, mid_, ROWS, HID, DIM);
        gemm_mma<2><<<dim3(DIM / 128, MG), 256, GEMM_SMEM>>>(
            mid_, w2T_ + (size_t)l * DIM * HID, mlp_b2 + (size_t)l * DIM,
            h_, h_, ROWS, DIM, HID);
    }

    ln_cls_kernel<<<BATCH, 256>>>(lnf_g, lnf_b, 1e-6f);
    head_kernel<<<dim3(4, BATCH), 256>>>(head_w, head_b, out);
}